// round 16
// baseline (speedup 1.0000x reference)
#include <cuda_runtime.h>
#include <cuda_bf16.h>
#include <cuda_fp16.h>
#include <cstdint>

#define NPIX   262144      // 512*512
#define HI     128
#define WI     128
#define CCH    64
#define NOUT   576         // C*KS*KS

// ---------------- scratch (device globals; no allocation) ----------------
__device__ __half        g_H2f[(size_t)NPIX * 256];  // fp16 relu(layer2), [pix][256]
__device__ __half        g_W3fh[NOUT * 256];         // fp16 of 64*W3, native [n][k]
__device__ __nv_bfloat16 g_W2h[256 * 64];            // bf16 hi of W2, native [n][k]
__device__ __nv_bfloat16 g_W2l[256 * 64];            // bf16 lo residual
__device__ __half g_XTh[2 * HI * WI * CCH];          // fp16 x transposed to [b][y][x][c]

__device__ __forceinline__ uint32_t smem_u32(const void* p) {
    uint32_t a;
    asm("{ .reg .u64 t; cvta.to.shared.u64 t, %1; cvt.u32.u64 %0, t; }" : "=r"(a) : "l"(p));
    return a;
}

#define CP16(dst, src) \
    asm volatile("cp.async.cg.shared.global [%0], [%1], 16;" :: "r"(dst), "l"(src))
#define CP_COMMIT() asm volatile("cp.async.commit_group;")
#define CP_WAITG(n) asm volatile("cp.async.wait_group %0;" :: "n"(n))

#define LDSM_X4(r0, r1, r2, r3, a) \
    asm volatile("ldmatrix.sync.aligned.m8n8.x4.shared.b16 {%0,%1,%2,%3}, [%4];" \
        : "=r"(r0), "=r"(r1), "=r"(r2), "=r"(r3) : "r"(a))

#define MMA16816BF(d, a0, a1, a2, a3, b0, b1) \
    asm volatile("mma.sync.aligned.m16n8k16.row.col.f32.bf16.bf16.f32 " \
        "{%0,%1,%2,%3}, {%4,%5,%6,%7}, {%8,%9}, {%0,%1,%2,%3};" \
        : "+f"((d)[0]), "+f"((d)[1]), "+f"((d)[2]), "+f"((d)[3]) \
        : "r"(a0), "r"(a1), "r"(a2), "r"(a3), "r"(b0), "r"(b1))

#define MMA16816F16(d, a0, a1, a2, a3, b0, b1) \
    asm volatile("mma.sync.aligned.m16n8k16.row.col.f32.f16.f16.f32 " \
        "{%0,%1,%2,%3}, {%4,%5,%6,%7}, {%8,%9}, {%0,%1,%2,%3};" \
        : "+f"((d)[0]), "+f"((d)[1]), "+f"((d)[2]), "+f"((d)[3]) \
        : "r"(a0), "r"(a1), "r"(a2), "r"(a3), "r"(b0), "r"(b1))

// ---------------- prep: weight splits ----------------
__global__ void prep_w(const float* __restrict__ W2, const float* __restrict__ W3) {
    int idx = blockIdx.x * blockDim.x + threadIdx.x;
    if (idx < 256 * 64) {
        float v = W2[idx];
        __nv_bfloat16 h = __float2bfloat16(v);
        g_W2h[idx] = h;
        g_W2l[idx] = __float2bfloat16(v - __bfloat162float(h));
    }
    if (idx < NOUT * 256) {
        g_W3fh[idx] = __float2half_rn(W3[idx] * 64.f);
    }
}

// ---------------- prep: x NCHW -> NHWC (fp16) ----------------
__global__ void prep_x(const float* __restrict__ x) {
    int o = blockIdx.x * blockDim.x + threadIdx.x;
    if (o >= 2 * HI * WI * CCH) return;
    int c = o & 63;
    int t = o >> 6;
    int xx = t & (WI - 1); t >>= 7;
    int y  = t & (HI - 1); t >>= 7;
    int b  = t;
    g_XTh[o] = __float2half_rn(x[(((b * CCH + c) * HI + y) * WI) + xx]);
}

// ---------------- K1: HMMA layer-2 GEMM with inline h1 producer ----------------
#define K1_AH 0
#define K1_AL 16384
#define K1_BH 32768
#define K1_BL 40960
#define K1_SMEM 49152

__global__ __launch_bounds__(256) void k1(const float* __restrict__ pose,
                                          const float* __restrict__ W1,
                                          const float* __restrict__ b1,
                                          const float* __restrict__ b2) {
    extern __shared__ __align__(128) char sm[];
    const uint32_t sbase = smem_u32(sm);
    __shared__ float w1s[192];
    __shared__ float b1s[64];

    const int tid = threadIdx.x;
    const int wid = tid >> 5, lane = tid & 31;
    const int n0 = blockIdx.x * 64;
    const int m0 = blockIdx.y * 128;

    if (tid < 192) w1s[tid] = W1[tid];
    if (tid < 64)  b1s[tid] = b1[tid];

#pragma unroll
    for (int i = 0; i < 2; i++) {
        int o = tid + i * 256;
        int row = o >> 3, g = o & 7;
        uint32_t dst = row * 128 + ((g * 16) ^ ((row & 7) << 4));
        size_t src = (size_t)(n0 + row) * 64 + g * 8;
        CP16(sbase + K1_BH + dst, g_W2h + src);
        CP16(sbase + K1_BL + dst, g_W2l + src);
    }
    CP_COMMIT();
    __syncthreads();

    {
        int row = tid >> 1;
        int ch0 = (tid & 1) * 32;
        int px = m0 + row;
        float p0 = pose[px], p1 = pose[NPIX + px], p2 = pose[2 * NPIX + px];
#pragma unroll
        for (int g = 0; g < 4; g++) {
            __nv_bfloat16 hi8[8], lo8[8];
#pragma unroll
            for (int j = 0; j < 8; j++) {
                int c = ch0 + g * 8 + j;
                float v = fmaf(w1s[c * 3], p0,
                          fmaf(w1s[c * 3 + 1], p1,
                          fmaf(w1s[c * 3 + 2], p2, b1s[c])));
                v = fmaxf(v, 0.f);
                __nv_bfloat16 h = __float2bfloat16(v);
                hi8[j] = h;
                lo8[j] = __float2bfloat16(v - __bfloat162float(h));
            }
            int grp = ch0 / 8 + g;
            uint32_t dst = row * 128 + ((grp * 16) ^ ((row & 7) << 4));
            *(uint4*)(sm + K1_AH + dst) = *(const uint4*)hi8;
            *(uint4*)(sm + K1_AL + dst) = *(const uint4*)lo8;
        }
    }
    CP_WAITG(0);
    __syncthreads();

    const int warpM = (wid >> 1) * 32;
    const int warpN = (wid & 1) * 32;
    const int q = lane >> 3, r8 = lane & 7;
    const int xm = r8 << 4;
    const int aRowL = warpM + ((q & 1) << 3) + r8;
    const int aKofs = (q >> 1) << 4;
    const int bRowL = warpN + ((q >> 1) << 3) + r8;
    const int bKofs = (q & 1) << 4;

    const uint32_t AH = sbase + K1_AH, AL = sbase + K1_AL;
    const uint32_t BH = sbase + K1_BH, BL = sbase + K1_BL;

    float acc[2][4][4] = {};
#pragma unroll
    for (int ks = 0; ks < 4; ks++) {
        int kbyte = ks * 32;
        uint32_t ah[8], al[8], bh[8], bl[8];
        LDSM_X4(ah[0], ah[1], ah[2], ah[3], AH + aRowL * 128        + ((kbyte + aKofs) ^ xm));
        LDSM_X4(ah[4], ah[5], ah[6], ah[7], AH + (aRowL + 16) * 128 + ((kbyte + aKofs) ^ xm));
        LDSM_X4(al[0], al[1], al[2], al[3], AL + aRowL * 128        + ((kbyte + aKofs) ^ xm));
        LDSM_X4(al[4], al[5], al[6], al[7], AL + (aRowL + 16) * 128 + ((kbyte + aKofs) ^ xm));
        LDSM_X4(bh[0], bh[1], bh[2], bh[3], BH + bRowL * 128        + ((kbyte + bKofs) ^ xm));
        LDSM_X4(bh[4], bh[5], bh[6], bh[7], BH + (bRowL + 16) * 128 + ((kbyte + bKofs) ^ xm));
        LDSM_X4(bl[0], bl[1], bl[2], bl[3], BL + bRowL * 128        + ((kbyte + bKofs) ^ xm));
        LDSM_X4(bl[4], bl[5], bl[6], bl[7], BL + (bRowL + 16) * 128 + ((kbyte + bKofs) ^ xm));
#pragma unroll
        for (int mi = 0; mi < 2; mi++)
#pragma unroll
            for (int ni = 0; ni < 4; ni++)
                MMA16816BF(acc[mi][ni], ah[mi * 4 + 0], ah[mi * 4 + 1], ah[mi * 4 + 2], ah[mi * 4 + 3],
                           bh[ni * 2 + 0], bh[ni * 2 + 1]);
#pragma unroll
        for (int mi = 0; mi < 2; mi++)
#pragma unroll
            for (int ni = 0; ni < 4; ni++)
                MMA16816BF(acc[mi][ni], ah[mi * 4 + 0], ah[mi * 4 + 1], ah[mi * 4 + 2], ah[mi * 4 + 3],
                           bl[ni * 2 + 0], bl[ni * 2 + 1]);
#pragma unroll
        for (int mi = 0; mi < 2; mi++)
#pragma unroll
            for (int ni = 0; ni < 4; ni++)
                MMA16816BF(acc[mi][ni], al[mi * 4 + 0], al[mi * 4 + 1], al[mi * 4 + 2], al[mi * 4 + 3],
                           bh[ni * 2 + 0], bh[ni * 2 + 1]);
    }

    const int g = lane >> 2, t = lane & 3;
#pragma unroll
    for (int mi = 0; mi < 2; mi++) {
#pragma unroll
        for (int ni = 0; ni < 4; ni++) {
            int nc = n0 + warpN + ni * 8 + 2 * t;
            float bv0 = b2[nc], bv1 = b2[nc + 1];
#pragma unroll
            for (int r = 0; r < 2; r++) {
                int px = m0 + warpM + mi * 16 + g + r * 8;
                float v0 = fmaxf(acc[mi][ni][2 * r + 0] + bv0, 0.f);
                float v1 = fmaxf(acc[mi][ni][2 * r + 1] + bv1, 0.f);
                __half2 hp;
                hp.x = __float2half_rn(v0);
                hp.y = __float2half_rn(v1);
                *(__half2*)&g_H2f[(size_t)px * 256 + nc] = hp;
            }
        }
    }
}

// ---------------- K2F: fused GEMM + softmax + gather (no global logits) ----------------
// CTA: 256 thr, M=128 px, loops 9 n-tiles x 4 k-chunks (36 pipelined chunks).
// Logits kept in smem (fp16, row stride 584 halves); epilogue does k3's work.
#define KC2      64
#define NQ       36                 // 9 n-tiles * 4 chunks
#define A_OFF    0
#define BH2_OFF  16384
#define STAGE2   24576
#define L_STR    584                // halves per logit row (bank-conflict pad)
#define LG_BYTES (128 * L_STR * 2)  // 149504
#define ST_BASE  LG_BYTES
#define K2_SMEM  (LG_BYTES + 2 * STAGE2)   // 198656

struct K2Geom {
    int aRow[4], aDst[4], bRow[2], bDst[2], grp8;
};

__device__ __forceinline__ void k2_issue(uint32_t sb, int m0, int q, const K2Geom& g) {
    int nt = q >> 2, kb = (q & 3) * KC2;
#pragma unroll
    for (int i = 0; i < 4; i++) {
        size_t asrc = (size_t)(m0 + g.aRow[i]) * 256 + kb + g.grp8;
        CP16(sb + A_OFF + g.aDst[i], g_H2f + asrc);
    }
#pragma unroll
    for (int i = 0; i < 2; i++) {
        size_t bsrc = (size_t)(nt * 64 + g.bRow[i]) * 256 + kb + g.grp8;
        CP16(sb + BH2_OFF + g.bDst[i], g_W3fh + bsrc);
    }
    CP_COMMIT();
}

__global__ __launch_bounds__(256, 1) void k2f(const float* __restrict__ b3,
                                              const int* __restrict__ mY,
                                              const int* __restrict__ mX,
                                              float* __restrict__ out) {
    extern __shared__ __align__(128) char sm[];
    const uint32_t sbase = smem_u32(sm);
    __half* lg = (__half*)sm;                       // logits [128][L_STR]
    float*  so = (float*)(sm + ST_BASE);            // output staging (reuses stages)
    const int tid = threadIdx.x;
    const int wid = tid >> 5, lane = tid & 31;
    const int m0 = blockIdx.x * 128;

    K2Geom gm;
    gm.grp8 = (tid & 7) * 8;
#pragma unroll
    for (int i = 0; i < 4; i++) {
        int o = tid + i * 256;
        int row = o >> 3, grp = o & 7;
        gm.aRow[i] = row;
        gm.aDst[i] = row * 128 + ((grp * 16) ^ ((row & 7) << 4));
    }
#pragma unroll
    for (int i = 0; i < 2; i++) {
        int o = tid + i * 256;
        int row = o >> 3, grp = o & 7;
        gm.bRow[i] = row;
        gm.bDst[i] = row * 128 + ((grp * 16) ^ ((row & 7) << 4));
    }

    uint32_t stb = sbase + ST_BASE;
    k2_issue(stb + 0 * STAGE2, m0, 0, gm);
    k2_issue(stb + 1 * STAGE2, m0, 1, gm);

    const int warpM = (wid >> 1) * 32;
    const int warpN = (wid & 1) * 32;
    const int q = lane >> 3, r8 = lane & 7;
    const int xm = r8 << 4;
    const int aRowL = warpM + ((q & 1) << 3) + r8;
    const int aKofs = (q >> 1) << 4;
    const int bRowL = warpN + ((q >> 1) << 3) + r8;
    const int bKofs = (q & 1) << 4;
    const int g = lane >> 2, t = lane & 3;
    const float SC = 1.f / 64.f;

    float acc[2][4][4] = {};

#pragma unroll 1
    for (int c = 0; c < NQ; c++) {
        if (c < NQ - 1) { CP_WAITG(1); } else { CP_WAITG(0); }
        __syncthreads();

        uint32_t Sb = stb + (c & 1) * STAGE2;
        uint32_t AA = Sb + A_OFF, BH = Sb + BH2_OFF;

#pragma unroll
        for (int ks = 0; ks < 4; ks++) {
            int kbyte = ks * 32;
            uint32_t a[8], bh[8];
            LDSM_X4(a[0], a[1], a[2], a[3], AA + aRowL * 128        + ((kbyte + aKofs) ^ xm));
            LDSM_X4(a[4], a[5], a[6], a[7], AA + (aRowL + 16) * 128 + ((kbyte + aKofs) ^ xm));
            LDSM_X4(bh[0], bh[1], bh[2], bh[3], BH + bRowL * 128        + ((kbyte + bKofs) ^ xm));
            LDSM_X4(bh[4], bh[5], bh[6], bh[7], BH + (bRowL + 16) * 128 + ((kbyte + bKofs) ^ xm));
#pragma unroll
            for (int mi = 0; mi < 2; mi++)
#pragma unroll
                for (int ni = 0; ni < 4; ni++)
                    MMA16816F16(acc[mi][ni], a[mi * 4 + 0], a[mi * 4 + 1], a[mi * 4 + 2], a[mi * 4 + 3],
                                bh[ni * 2 + 0], bh[ni * 2 + 1]);
        }

        if ((c & 3) == 3) {
            // n-tile done: bias + scale, store fp16 logits to smem, reset acc
            int nt = c >> 2;
#pragma unroll
            for (int mi = 0; mi < 2; mi++) {
#pragma unroll
                for (int ni = 0; ni < 4; ni++) {
                    int nc = nt * 64 + warpN + ni * 8 + 2 * t;
                    float2 bvv = *(const float2*)&b3[nc];
#pragma unroll
                    for (int r = 0; r < 2; r++) {
                        int mgl = warpM + mi * 16 + g + r * 8;
                        __half2 s;
                        s.x = __float2half_rn(fmaf(acc[mi][ni][2 * r + 0], SC, bvv.x));
                        s.y = __float2half_rn(fmaf(acc[mi][ni][2 * r + 1], SC, bvv.y));
                        *(__half2*)&lg[mgl * L_STR + nc] = s;
                        acc[mi][ni][2 * r + 0] = 0.f;
                        acc[mi][ni][2 * r + 1] = 0.f;
                    }
                }
            }
        }
        __syncthreads();
        if (c < NQ - 2)
            k2_issue(stb + (c & 1) * STAGE2, m0, c + 2, gm);
    }
    __syncthreads();   // all logits visible

    // ---- epilogue: softmax + gather, 4 groups of 32 px ----
#pragma unroll 1
    for (int grp = 0; grp < 4; grp++) {
#pragma unroll 1
        for (int pi = 0; pi < 4; pi++) {
            int pxl = grp * 32 + wid * 4 + pi;
            int px = m0 + pxl;
            int Y = mY[px], X = mX[px];

            float w[18];
            {
                const __half2* l2 = (const __half2*)(lg + pxl * L_STR + lane * 18);
#pragma unroll
                for (int j = 0; j < 9; j++) {
                    float2 v = __half22float2(l2[j]);
                    w[2 * j] = v.x; w[2 * j + 1] = v.y;
                }
            }

            float sw0[9], sw1[9];
            float m0v = w[0], m1v = w[9];
#pragma unroll
            for (int j = 1; j < 9; j++) { m0v = fmaxf(m0v, w[j]); m1v = fmaxf(m1v, w[9 + j]); }
            float s0 = 0.f, s1 = 0.f;
#pragma unroll
            for (int j = 0; j < 9; j++) {
                sw0[j] = __expf(w[j] - m0v);     s0 += sw0[j];
                sw1[j] = __expf(w[9 + j] - m1v); s1 += sw1[j];
            }
            float inv0 = 1.f / s0, inv1 = 1.f / s1;

            float a0x = 0.f, a0y = 0.f, a1x = 0.f, a1y = 0.f;
#pragma unroll
            for (int j = 0; j < 9; j++) {
                int yy = Y + j / 3 - 1;
                int xx = X + j % 3 - 1;
                if ((unsigned)yy < HI && (unsigned)xx < WI) {
                    const __half2* base0 = (const __half2*)(g_XTh + (size_t)((0 * HI + yy) * WI + xx) * CCH + 2 * lane);
                    const __half2* base1 = (const __half2*)(g_XTh + (size_t)((1 * HI + yy) * WI + xx) * CCH + 2 * lane);
                    float2 gv0 = __half22float2(*base0);
                    float2 gv1 = __half22float2(*base1);
                    a0x += sw0[j] * gv0.x; a0y += sw1[j] * gv0.y;
                    a1x += sw0[j] * gv1.x; a1y += sw1[j] * gv1.y;
                }
            }
            int pl = pxl & 31;
            so[(0 * 64 + 2 * lane    ) * 33 + pl] = a0x * inv0;
            so[(0 * 64 + 2 * lane + 1) * 33 + pl] = a0y * inv1;
            so[(1 * 64 + 2 * lane    ) * 33 + pl] = a1x * inv0;
            so[(1 * 64 + 2 * lane + 1) * 33 + pl] = a1y * inv1;
        }
        __syncthreads();

        int row = tid >> 1, half = (tid & 1) * 16;
        float* orow = out + (size_t)row * NPIX + m0 + grp * 32 + half;
        const float* srow = so + row * 33 + half;
#pragma unroll
        for (int i = 0; i < 4; i++) {
            float4 v = {srow[4 * i], srow[4 * i + 1], srow[4 * i + 2], srow[4 * i + 3]};
            *(float4*)&orow[4 * i] = v;
        }
        __syncthreads();
    }
}

// ---------------- launch ----------------
extern "C" void kernel_launch(void* const* d_in, const int* in_sizes, int n_in,
                              void* d_out, int out_size) {
    const float* x    = (const float*)d_in[0];
    const float* pose = (const float*)d_in[1];
    const float* W1   = (const float*)d_in[2];
    const float* b1   = (const float*)d_in[3];
    const float* W2   = (const float*)d_in[4];
    const float* b2   = (const float*)d_in[5];
    const float* W3   = (const float*)d_in[6];
    const float* b3   = (const float*)d_in[7];
    const int*   mY   = (const int*)d_in[8];
    const int*   mX   = (const int*)d_in[9];
    float* out = (float*)d_out;

    cudaFuncSetAttribute(k2f, cudaFuncAttributeMaxDynamicSharedMemorySize, K2_SMEM);
    cudaFuncSetAttribute(k1, cudaFuncAttributeMaxDynamicSharedMemorySize, K1_SMEM);

    prep_w<<<(NOUT * 256 + 255) / 256, 256>>>(W2, W3);
    prep_x<<<(2 * HI * WI * CCH + 255) / 256, 256>>>(x);
    dim3 g1(256 / 64, NPIX / 128);
    k1<<<g1, 256, K1_SMEM>>>(pose, W1, b1, b2);
    k2f<<<NPIX / 128, 256, K2_SMEM>>>(b3, mY, mX, out);
}

// round 17
// speedup vs baseline: 1.1775x; 1.1775x over previous
#include <cuda_runtime.h>
#include <cuda_bf16.h>
#include <cuda_fp16.h>
#include <cstdint>

#define NPIX   262144      // 512*512
#define HI     128
#define WI     128
#define CCH    64
#define NOUT   576         // C*KS*KS

// ---------------- scratch (device globals; no allocation) ----------------
__device__ __half        g_H2f[(size_t)NPIX * 256];  // fp16 relu(layer2), [pix][256]
__device__ __half        g_W3fh[NOUT * 256];         // fp16 of 64*W3, native [n][k]
__device__ __nv_bfloat16 g_W2h[256 * 64];            // bf16 hi of W2, native [n][k]
__device__ __nv_bfloat16 g_W2l[256 * 64];            // bf16 lo residual
__device__ __half g_W3Oh[(size_t)NPIX * NOUT];       // fp16 layer-3 logits, [pix][576]
__device__ __half g_XTh[2 * HI * WI * CCH];          // fp16 x transposed to [b][y][x][c]

__device__ __forceinline__ uint32_t smem_u32(const void* p) {
    uint32_t a;
    asm("{ .reg .u64 t; cvta.to.shared.u64 t, %1; cvt.u32.u64 %0, t; }" : "=r"(a) : "l"(p));
    return a;
}

#define CP16(dst, src) \
    asm volatile("cp.async.cg.shared.global [%0], [%1], 16;" :: "r"(dst), "l"(src))
#define CP_COMMIT() asm volatile("cp.async.commit_group;")
#define CP_WAITG(n) asm volatile("cp.async.wait_group %0;" :: "n"(n))

#define LDSM_X4(r0, r1, r2, r3, a) \
    asm volatile("ldmatrix.sync.aligned.m8n8.x4.shared.b16 {%0,%1,%2,%3}, [%4];" \
        : "=r"(r0), "=r"(r1), "=r"(r2), "=r"(r3) : "r"(a))

#define MMA16816BF(d, a0, a1, a2, a3, b0, b1) \
    asm volatile("mma.sync.aligned.m16n8k16.row.col.f32.bf16.bf16.f32 " \
        "{%0,%1,%2,%3}, {%4,%5,%6,%7}, {%8,%9}, {%0,%1,%2,%3};" \
        : "+f"((d)[0]), "+f"((d)[1]), "+f"((d)[2]), "+f"((d)[3]) \
        : "r"(a0), "r"(a1), "r"(a2), "r"(a3), "r"(b0), "r"(b1))

#define MMA16816F16(d, a0, a1, a2, a3, b0, b1) \
    asm volatile("mma.sync.aligned.m16n8k16.row.col.f32.f16.f16.f32 " \
        "{%0,%1,%2,%3}, {%4,%5,%6,%7}, {%8,%9}, {%0,%1,%2,%3};" \
        : "+f"((d)[0]), "+f"((d)[1]), "+f"((d)[2]), "+f"((d)[3]) \
        : "r"(a0), "r"(a1), "r"(a2), "r"(a3), "r"(b0), "r"(b1))

// ---------------- prep: weight splits ----------------
__global__ void prep_w(const float* __restrict__ W2, const float* __restrict__ W3) {
    int idx = blockIdx.x * blockDim.x + threadIdx.x;
    if (idx < 256 * 64) {
        float v = W2[idx];
        __nv_bfloat16 h = __float2bfloat16(v);
        g_W2h[idx] = h;
        g_W2l[idx] = __float2bfloat16(v - __bfloat162float(h));
    }
    if (idx < NOUT * 256) {
        g_W3fh[idx] = __float2half_rn(W3[idx] * 64.f);
    }
}

// ---------------- prep: x NCHW -> NHWC (fp16) ----------------
__global__ void prep_x(const float* __restrict__ x) {
    int o = blockIdx.x * blockDim.x + threadIdx.x;
    if (o >= 2 * HI * WI * CCH) return;
    int c = o & 63;
    int t = o >> 6;
    int xx = t & (WI - 1); t >>= 7;
    int y  = t & (HI - 1); t >>= 7;
    int b  = t;
    g_XTh[o] = __float2half_rn(x[(((b * CCH + c) * HI + y) * WI) + xx]);
}

// ---------------- K1: HMMA layer-2 GEMM with inline h1 producer ----------------
#define K1_AH 0
#define K1_AL 16384
#define K1_BH 32768
#define K1_BL 40960
#define K1_SMEM 49152

__global__ __launch_bounds__(256) void k1(const float* __restrict__ pose,
                                          const float* __restrict__ W1,
                                          const float* __restrict__ b1,
                                          const float* __restrict__ b2) {
    extern __shared__ __align__(128) char sm[];
    const uint32_t sbase = smem_u32(sm);
    __shared__ float w1s[192];
    __shared__ float b1s[64];

    const int tid = threadIdx.x;
    const int wid = tid >> 5, lane = tid & 31;
    const int n0 = blockIdx.x * 64;
    const int m0 = blockIdx.y * 128;

    if (tid < 192) w1s[tid] = W1[tid];
    if (tid < 64)  b1s[tid] = b1[tid];

#pragma unroll
    for (int i = 0; i < 2; i++) {
        int o = tid + i * 256;
        int row = o >> 3, g = o & 7;
        uint32_t dst = row * 128 + ((g * 16) ^ ((row & 7) << 4));
        size_t src = (size_t)(n0 + row) * 64 + g * 8;
        CP16(sbase + K1_BH + dst, g_W2h + src);
        CP16(sbase + K1_BL + dst, g_W2l + src);
    }
    CP_COMMIT();
    __syncthreads();

    {
        int row = tid >> 1;
        int ch0 = (tid & 1) * 32;
        int px = m0 + row;
        float p0 = pose[px], p1 = pose[NPIX + px], p2 = pose[2 * NPIX + px];
#pragma unroll
        for (int g = 0; g < 4; g++) {
            __nv_bfloat16 hi8[8], lo8[8];
#pragma unroll
            for (int j = 0; j < 8; j++) {
                int c = ch0 + g * 8 + j;
                float v = fmaf(w1s[c * 3], p0,
                          fmaf(w1s[c * 3 + 1], p1,
                          fmaf(w1s[c * 3 + 2], p2, b1s[c])));
                v = fmaxf(v, 0.f);
                __nv_bfloat16 h = __float2bfloat16(v);
                hi8[j] = h;
                lo8[j] = __float2bfloat16(v - __bfloat162float(h));
            }
            int grp = ch0 / 8 + g;
            uint32_t dst = row * 128 + ((grp * 16) ^ ((row & 7) << 4));
            *(uint4*)(sm + K1_AH + dst) = *(const uint4*)hi8;
            *(uint4*)(sm + K1_AL + dst) = *(const uint4*)lo8;
        }
    }
    CP_WAITG(0);
    __syncthreads();

    const int warpM = (wid >> 1) * 32;
    const int warpN = (wid & 1) * 32;
    const int q = lane >> 3, r8 = lane & 7;
    const int xm = r8 << 4;
    const int aRowL = warpM + ((q & 1) << 3) + r8;
    const int aKofs = (q >> 1) << 4;
    const int bRowL = warpN + ((q >> 1) << 3) + r8;
    const int bKofs = (q & 1) << 4;

    const uint32_t AH = sbase + K1_AH, AL = sbase + K1_AL;
    const uint32_t BH = sbase + K1_BH, BL = sbase + K1_BL;

    float acc[2][4][4] = {};
#pragma unroll
    for (int ks = 0; ks < 4; ks++) {
        int kbyte = ks * 32;
        uint32_t ah[8], al[8], bh[8], bl[8];
        LDSM_X4(ah[0], ah[1], ah[2], ah[3], AH + aRowL * 128        + ((kbyte + aKofs) ^ xm));
        LDSM_X4(ah[4], ah[5], ah[6], ah[7], AH + (aRowL + 16) * 128 + ((kbyte + aKofs) ^ xm));
        LDSM_X4(al[0], al[1], al[2], al[3], AL + aRowL * 128        + ((kbyte + aKofs) ^ xm));
        LDSM_X4(al[4], al[5], al[6], al[7], AL + (aRowL + 16) * 128 + ((kbyte + aKofs) ^ xm));
        LDSM_X4(bh[0], bh[1], bh[2], bh[3], BH + bRowL * 128        + ((kbyte + bKofs) ^ xm));
        LDSM_X4(bh[4], bh[5], bh[6], bh[7], BH + (bRowL + 16) * 128 + ((kbyte + bKofs) ^ xm));
        LDSM_X4(bl[0], bl[1], bl[2], bl[3], BL + bRowL * 128        + ((kbyte + bKofs) ^ xm));
        LDSM_X4(bl[4], bl[5], bl[6], bl[7], BL + (bRowL + 16) * 128 + ((kbyte + bKofs) ^ xm));
#pragma unroll
        for (int mi = 0; mi < 2; mi++)
#pragma unroll
            for (int ni = 0; ni < 4; ni++)
                MMA16816BF(acc[mi][ni], ah[mi * 4 + 0], ah[mi * 4 + 1], ah[mi * 4 + 2], ah[mi * 4 + 3],
                           bh[ni * 2 + 0], bh[ni * 2 + 1]);
#pragma unroll
        for (int mi = 0; mi < 2; mi++)
#pragma unroll
            for (int ni = 0; ni < 4; ni++)
                MMA16816BF(acc[mi][ni], ah[mi * 4 + 0], ah[mi * 4 + 1], ah[mi * 4 + 2], ah[mi * 4 + 3],
                           bl[ni * 2 + 0], bl[ni * 2 + 1]);
#pragma unroll
        for (int mi = 0; mi < 2; mi++)
#pragma unroll
            for (int ni = 0; ni < 4; ni++)
                MMA16816BF(acc[mi][ni], al[mi * 4 + 0], al[mi * 4 + 1], al[mi * 4 + 2], al[mi * 4 + 3],
                           bh[ni * 2 + 0], bh[ni * 2 + 1]);
    }

    const int g = lane >> 2, t = lane & 3;
#pragma unroll
    for (int mi = 0; mi < 2; mi++) {
#pragma unroll
        for (int ni = 0; ni < 4; ni++) {
            int nc = n0 + warpN + ni * 8 + 2 * t;
            float bv0 = b2[nc], bv1 = b2[nc + 1];
#pragma unroll
            for (int r = 0; r < 2; r++) {
                int px = m0 + warpM + mi * 16 + g + r * 8;
                float v0 = fmaxf(acc[mi][ni][2 * r + 0] + bv0, 0.f);
                float v1 = fmaxf(acc[mi][ni][2 * r + 1] + bv1, 0.f);
                __half2 hp;
                hp.x = __float2half_rn(v0);
                hp.y = __float2half_rn(v1);
                *(__half2*)&g_H2f[(size_t)px * 256 + nc] = hp;
            }
        }
    }
}

// ---------------- K2: single-product fp16 HMMA GEMM, 3-stage pipeline ----------------
#define KC2      64
#define NCHUNK2  4
#define A_OFF    0
#define BH2_OFF  16384
#define STAGE2   24576
#define K2_SMEM  (3 * STAGE2)     // 73728

struct K2Geom {
    int aRow[4], aDst[4], bRow[2], bDst[2], grp8;
};

__device__ __forceinline__ void k2_issue(uint32_t sb, int m0, int n0, int kb, const K2Geom& g) {
#pragma unroll
    for (int i = 0; i < 4; i++) {
        size_t asrc = (size_t)(m0 + g.aRow[i]) * 256 + kb + g.grp8;
        CP16(sb + A_OFF + g.aDst[i], g_H2f + asrc);
    }
#pragma unroll
    for (int i = 0; i < 2; i++) {
        size_t bsrc = (size_t)(n0 + g.bRow[i]) * 256 + kb + g.grp8;
        CP16(sb + BH2_OFF + g.bDst[i], g_W3fh + bsrc);
    }
    CP_COMMIT();
}

__global__ __launch_bounds__(256, 2) void k2(const float* __restrict__ b3) {
    extern __shared__ __align__(128) char smem[];
    const uint32_t sbase = smem_u32(smem);
    const int tid = threadIdx.x;
    const int wid = tid >> 5, lane = tid & 31;

    const int n0 = blockIdx.x * 64;
    const int m0 = blockIdx.y * 128;

    K2Geom gm;
    gm.grp8 = (tid & 7) * 8;
#pragma unroll
    for (int i = 0; i < 4; i++) {
        int o = tid + i * 256;
        int row = o >> 3, grp = o & 7;
        gm.aRow[i] = row;
        gm.aDst[i] = row * 128 + ((grp * 16) ^ ((row & 7) << 4));
    }
#pragma unroll
    for (int i = 0; i < 2; i++) {
        int o = tid + i * 256;
        int row = o >> 3, grp = o & 7;
        gm.bRow[i] = row;
        gm.bDst[i] = row * 128 + ((grp * 16) ^ ((row & 7) << 4));
    }

    // 3-stage ring, prefetch distance 2
    k2_issue(sbase + 0 * STAGE2, m0, n0, 0 * KC2, gm);
    k2_issue(sbase + 1 * STAGE2, m0, n0, 1 * KC2, gm);

    const int warpM = (wid >> 1) * 32;
    const int warpN = (wid & 1) * 32;
    const int q = lane >> 3, r8 = lane & 7;
    const int xm = r8 << 4;
    const int aRowL = warpM + ((q & 1) << 3) + r8;
    const int aKofs = (q >> 1) << 4;
    const int bRowL = warpN + ((q >> 1) << 3) + r8;
    const int bKofs = (q & 1) << 4;

    float acc[2][4][4] = {};

#pragma unroll 1
    for (int c = 0; c < NCHUNK2; c++) {
        if (c < NCHUNK2 - 1) { CP_WAITG(1); } else { CP_WAITG(0); }
        __syncthreads();

        int cur = (c < 3) ? c : c - 3;
        uint32_t Sb = sbase + cur * STAGE2;
        uint32_t AA = Sb + A_OFF, BH = Sb + BH2_OFF;

#pragma unroll
        for (int ks = 0; ks < 4; ks++) {
            int kbyte = ks * 32;
            uint32_t a[8], bh[8];
            LDSM_X4(a[0], a[1], a[2], a[3], AA + aRowL * 128        + ((kbyte + aKofs) ^ xm));
            LDSM_X4(a[4], a[5], a[6], a[7], AA + (aRowL + 16) * 128 + ((kbyte + aKofs) ^ xm));
            LDSM_X4(bh[0], bh[1], bh[2], bh[3], BH + bRowL * 128        + ((kbyte + bKofs) ^ xm));
            LDSM_X4(bh[4], bh[5], bh[6], bh[7], BH + (bRowL + 16) * 128 + ((kbyte + bKofs) ^ xm));
#pragma unroll
            for (int mi = 0; mi < 2; mi++)
#pragma unroll
                for (int ni = 0; ni < 4; ni++)
                    MMA16816F16(acc[mi][ni], a[mi * 4 + 0], a[mi * 4 + 1], a[mi * 4 + 2], a[mi * 4 + 3],
                                bh[ni * 2 + 0], bh[ni * 2 + 1]);
        }
        // Issue chunk c+2 into stage (c+2)%3: that stage was last read in iter c-1,
        // and every warp passed this iter's __syncthreads after finishing it. No tail sync.
        if (c < NCHUNK2 - 2) {
            int nxt = c + 2;
            int ns = (nxt < 3) ? nxt : nxt - 3;
            k2_issue(sbase + ns * STAGE2, m0, n0, nxt * KC2, gm);
        }
    }

    const float SC = 1.f / 64.f;
    const int g = lane >> 2, t = lane & 3;
#pragma unroll
    for (int mi = 0; mi < 2; mi++) {
#pragma unroll
        for (int ni = 0; ni < 4; ni++) {
            int mg = m0 + warpM + mi * 16 + g;
            int nc = n0 + warpN + ni * 8 + 2 * t;
            float2 bvv = *(const float2*)&b3[nc];
            __half2 s0, s1;
            s0.x = __float2half_rn(fmaf(acc[mi][ni][0], SC, bvv.x));
            s0.y = __float2half_rn(fmaf(acc[mi][ni][1], SC, bvv.y));
            s1.x = __float2half_rn(fmaf(acc[mi][ni][2], SC, bvv.x));
            s1.y = __float2half_rn(fmaf(acc[mi][ni][3], SC, bvv.y));
            *(__half2*)&g_W3Oh[(size_t)mg * NOUT + nc] = s0;
            *(__half2*)&g_W3Oh[(size_t)(mg + 8) * NOUT + nc] = s1;
        }
    }
}

// ---------------- K3: smem-staged fp16 logits + softmax + fp16 gather ----------------
__global__ __launch_bounds__(256) void k3(const int* __restrict__ mY,
                                          const int* __restrict__ mX,
                                          float* __restrict__ out) {
    __shared__ float so[128 * 33];
    __shared__ __align__(16) __half lg[8][NOUT];  // 9.2 KB
    const int tid = threadIdx.x;
    const int wid = tid >> 5, lane = tid & 31;
    const int px0 = blockIdx.x * 32;

#pragma unroll 1
    for (int pi = 0; pi < 4; pi++) {
        int pxl = wid * 4 + pi;
        int px = px0 + pxl;
        int Y = mY[px], X = mX[px];

        {
            const uint4* src4 = (const uint4*)(g_W3Oh + (size_t)px * NOUT);
            uint4* dst4 = (uint4*)lg[wid];
#pragma unroll
            for (int it = 0; it < 3; it++) {
                int i = it * 32 + lane;
                if (i < 72) dst4[i] = src4[i];
            }
        }
        __syncwarp();

        float w[18];
        {
            const __half2* l2 = (const __half2*)(lg[wid] + lane * 18);
#pragma unroll
            for (int j = 0; j < 9; j++) {
                float2 v = __half22float2(l2[j]);
                w[2 * j] = v.x; w[2 * j + 1] = v.y;
            }
        }
        __syncwarp();

        float sw0[9], sw1[9];
        float m0v = w[0], m1v = w[9];
#pragma unroll
        for (int j = 1; j < 9; j++) { m0v = fmaxf(m0v, w[j]); m1v = fmaxf(m1v, w[9 + j]); }
        float s0 = 0.f, s1 = 0.f;
#pragma unroll
        for (int j = 0; j < 9; j++) {
            sw0[j] = __expf(w[j] - m0v);     s0 += sw0[j];
            sw1[j] = __expf(w[9 + j] - m1v); s1 += sw1[j];
        }
        float inv0 = 1.f / s0, inv1 = 1.f / s1;

        float a0x = 0.f, a0y = 0.f, a1x = 0.f, a1y = 0.f;
#pragma unroll
        for (int j = 0; j < 9; j++) {
            int yy = Y + j / 3 - 1;
            int xx = X + j % 3 - 1;
            if ((unsigned)yy < HI && (unsigned)xx < WI) {
                const __half2* base0 = (const __half2*)(g_XTh + (size_t)((0 * HI + yy) * WI + xx) * CCH + 2 * lane);
                const __half2* base1 = (const __half2*)(g_XTh + (size_t)((1 * HI + yy) * WI + xx) * CCH + 2 * lane);
                float2 gv0 = __half22float2(*base0);
                float2 gv1 = __half22float2(*base1);
                a0x += sw0[j] * gv0.x; a0y += sw1[j] * gv0.y;
                a1x += sw0[j] * gv1.x; a1y += sw1[j] * gv1.y;
            }
        }
        so[(0 * 64 + 2 * lane    ) * 33 + pxl] = a0x * inv0;
        so[(0 * 64 + 2 * lane + 1) * 33 + pxl] = a0y * inv1;
        so[(1 * 64 + 2 * lane    ) * 33 + pxl] = a1x * inv0;
        so[(1 * 64 + 2 * lane + 1) * 33 + pxl] = a1y * inv1;
    }
    __syncthreads();

    int row = tid >> 1, half = (tid & 1) * 16;
    float* orow = out + (size_t)row * NPIX + px0 + half;
    const float* srow = so + row * 33 + half;
#pragma unroll
    for (int i = 0; i < 4; i++) {
        float4 v = {srow[4 * i], srow[4 * i + 1], srow[4 * i + 2], srow[4 * i + 3]};
        *(float4*)&orow[4 * i] = v;
    }
}

// ---------------- launch ----------------
extern "C" void kernel_launch(void* const* d_in, const int* in_sizes, int n_in,
                              void* d_out, int out_size) {
    const float* x    = (const float*)d_in[0];
    const float* pose = (const float*)d_in[1];
    const float* W1   = (const float*)d_in[2];
    const float* b1   = (const float*)d_in[3];
    const float* W2   = (const float*)d_in[4];
    const float* b2   = (const float*)d_in[5];
    const float* W3   = (const float*)d_in[6];
    const float* b3   = (const float*)d_in[7];
    const int*   mY   = (const int*)d_in[8];
    const int*   mX   = (const int*)d_in[9];
    float* out = (float*)d_out;

    cudaFuncSetAttribute(k2, cudaFuncAttributeMaxDynamicSharedMemorySize, K2_SMEM);
    cudaFuncSetAttribute(k1, cudaFuncAttributeMaxDynamicSharedMemorySize, K1_SMEM);

    prep_w<<<(NOUT * 256 + 255) / 256, 256>>>(W2, W3);
    prep_x<<<(2 * HI * WI * CCH + 255) / 256, 256>>>(x);
    dim3 g1(256 / 64, NPIX / 128);
    k1<<<g1, 256, K1_SMEM>>>(pose, W1, b1, b2);
    dim3 g2(NOUT / 64, NPIX / 128);
    k2<<<g2, 256, K2_SMEM>>>(b3);
    k3<<<NPIX / 32, 256>>>(mY, mX, out);
}